// round 2
// baseline (speedup 1.0000x reference)
#include <cuda_runtime.h>

#define N_ROWS   400000
#define C        64
#define KTAPS    27
#define TILE_M   128
#define NTHREADS 256
#define FS_STRIDE 65          // pad to kill smem bank conflicts on feature reads
#define EPS_F    1e-5f

// Per-channel statistics accumulators (scratch: __device__ globals, no allocation)
__device__ float g_sum[C];
__device__ float g_sumsq[C];

// smem: feat[128][65] + w[64][64] (as float4[64][16]) + s_sum[64] + s_sq[64]
#define SMEM_FLOATS (TILE_M * FS_STRIDE + C * C + 2 * C)
#define SMEM_BYTES  (SMEM_FLOATS * 4)

__global__ void zero_stats_kernel() {
    int t = threadIdx.x;
    if (t < C) { g_sum[t] = 0.0f; g_sumsq[t] = 0.0f; }
}

extern __shared__ float smem[];

__global__ __launch_bounds__(NTHREADS)
void conv_stats_kernel(const float* __restrict__ features,
                       const int*   __restrict__ nmap,
                       const float* __restrict__ weight,
                       float*       __restrict__ out)
{
    float*  fs   = smem;                                   // TILE_M * FS_STRIDE
    float4* ws4  = (float4*)(smem + TILE_M * FS_STRIDE);   // 64 rows x 16 float4
    float*  ssum = (float*)(ws4 + C * (C / 4));            // 64
    float*  ssq  = ssum + C;                               // 64

    const int tid  = threadIdx.x;
    const int row0 = blockIdx.x * TILE_M;

    if (tid < C) { ssum[tid] = 0.0f; ssq[tid] = 0.0f; }

    // gather mapping: 16 threads per row, one float4 each
    const int lane_j = tid & 15;   // which float4 within the 64-float row
    const int rrow   = tid >> 4;   // starting row, step 16

    // compute mapping: 32 rowgroups (4 rows each) x 8 colgroups (8 cols each)
    const int rg = tid >> 3;       // 0..31
    const int cg = tid & 7;        // 0..7

    float acc[4][8];
#pragma unroll
    for (int i = 0; i < 4; ++i)
#pragma unroll
        for (int c = 0; c < 8; ++c) acc[i][c] = 0.0f;

    for (int k = 0; k < KTAPS; ++k) {
        __syncthreads();   // protect previous iteration's reads (and ssum init on k=0)

        // stage W_k [64 cin][64 cout] -> smem (contiguous, matches global layout)
        const float4* wg = (const float4*)(weight + k * C * C);
#pragma unroll
        for (int u = 0; u < 4; ++u)
            ws4[tid + u * NTHREADS] = wg[tid + u * NTHREADS];

        // gather 128 feature rows (float4 global loads, scalar smem stores)
#pragma unroll
        for (int rr = rrow; rr < TILE_M; rr += 16) {
            int idx = __ldg(&nmap[k * N_ROWS + row0 + rr]);
            float4 v = make_float4(0.f, 0.f, 0.f, 0.f);
            if (idx >= 0)
                v = __ldg(&((const float4*)features)[idx * 16 + lane_j]);
            float* d = fs + rr * FS_STRIDE + lane_j * 4;
            d[0] = v.x; d[1] = v.y; d[2] = v.z; d[3] = v.w;
        }
        __syncthreads();

        const float*  fr = fs + rg * 4 * FS_STRIDE;
        const float4* wp = ws4 + cg * 2;

#pragma unroll 16
        for (int j = 0; j < C; ++j) {
            float4 b0 = wp[j * 16];
            float4 b1 = wp[j * 16 + 1];
            float a0 = fr[j];
            float a1 = fr[FS_STRIDE + j];
            float a2 = fr[2 * FS_STRIDE + j];
            float a3 = fr[3 * FS_STRIDE + j];

            acc[0][0] += a0 * b0.x; acc[0][1] += a0 * b0.y;
            acc[0][2] += a0 * b0.z; acc[0][3] += a0 * b0.w;
            acc[0][4] += a0 * b1.x; acc[0][5] += a0 * b1.y;
            acc[0][6] += a0 * b1.z; acc[0][7] += a0 * b1.w;

            acc[1][0] += a1 * b0.x; acc[1][1] += a1 * b0.y;
            acc[1][2] += a1 * b0.z; acc[1][3] += a1 * b0.w;
            acc[1][4] += a1 * b1.x; acc[1][5] += a1 * b1.y;
            acc[1][6] += a1 * b1.z; acc[1][7] += a1 * b1.w;

            acc[2][0] += a2 * b0.x; acc[2][1] += a2 * b0.y;
            acc[2][2] += a2 * b0.z; acc[2][3] += a2 * b0.w;
            acc[2][4] += a2 * b1.x; acc[2][5] += a2 * b1.y;
            acc[2][6] += a2 * b1.z; acc[2][7] += a2 * b1.w;

            acc[3][0] += a3 * b0.x; acc[3][1] += a3 * b0.y;
            acc[3][2] += a3 * b0.z; acc[3][3] += a3 * b0.w;
            acc[3][4] += a3 * b1.x; acc[3][5] += a3 * b1.y;
            acc[3][6] += a3 * b1.z; acc[3][7] += a3 * b1.w;
        }
    }

    // write conv output (pre-norm) to d_out
    const int rbase = row0 + rg * 4;
    const int cbase = cg * 8;
#pragma unroll
    for (int i = 0; i < 4; ++i) {
        float4 o0 = make_float4(acc[i][0], acc[i][1], acc[i][2], acc[i][3]);
        float4 o1 = make_float4(acc[i][4], acc[i][5], acc[i][6], acc[i][7]);
        float4* dst = (float4*)(out + (size_t)(rbase + i) * C + cbase);
        dst[0] = o0;
        dst[1] = o1;
    }

    // per-channel partial sums: thread-local over its 4 rows, then smem atomics
#pragma unroll
    for (int c = 0; c < 8; ++c) {
        float s = acc[0][c] + acc[1][c] + acc[2][c] + acc[3][c];
        float q = acc[0][c] * acc[0][c] + acc[1][c] * acc[1][c]
                + acc[2][c] * acc[2][c] + acc[3][c] * acc[3][c];
        atomicAdd(&ssum[cbase + c], s);
        atomicAdd(&ssq[cbase + c], q);
    }
    __syncthreads();
    if (tid < C) {
        atomicAdd(&g_sum[tid],   ssum[tid]);
        atomicAdd(&g_sumsq[tid], ssq[tid]);
    }
}

__global__ __launch_bounds__(256)
void norm_relu_kernel(float* __restrict__ out,
                      const float* __restrict__ gamma,
                      const float* __restrict__ beta)
{
    __shared__ float sc[C], sh[C];
    int t = threadIdx.x;
    if (t < C) {
        const float invn = 1.0f / (float)N_ROWS;
        float mean = g_sum[t] * invn;
        float var  = g_sumsq[t] * invn - mean * mean;
        float inv  = rsqrtf(var + EPS_F);
        float g    = gamma[t] * inv;
        sc[t] = g;
        sh[t] = beta[t] - mean * g;
    }
    __syncthreads();

    const int total4 = N_ROWS * C / 4;   // 6.4M float4
    float4* o4 = (float4*)out;
    for (int i = blockIdx.x * blockDim.x + t; i < total4;
         i += gridDim.x * blockDim.x) {
        float4 v = o4[i];
        int cb = (i & 15) * 4;           // 16 float4 per 64-channel row
        v.x = fmaxf(fmaf(v.x, sc[cb + 0], sh[cb + 0]), 0.0f);
        v.y = fmaxf(fmaf(v.y, sc[cb + 1], sh[cb + 1]), 0.0f);
        v.z = fmaxf(fmaf(v.z, sc[cb + 2], sh[cb + 2]), 0.0f);
        v.w = fmaxf(fmaf(v.w, sc[cb + 3], sh[cb + 3]), 0.0f);
        o4[i] = v;
    }
}

extern "C" void kernel_launch(void* const* d_in, const int* in_sizes, int n_in,
                              void* d_out, int out_size)
{
    const float* features = (const float*)d_in[0];
    const int*   nmap     = (const int*)  d_in[1];
    const float* weight   = (const float*)d_in[2];
    const float* gamma    = (const float*)d_in[3];
    const float* beta     = (const float*)d_in[4];
    float* out = (float*)d_out;

    // >48KB dynamic smem opt-in (idempotent; not a stream op, capture-safe)
    cudaFuncSetAttribute(conv_stats_kernel,
                         cudaFuncAttributeMaxDynamicSharedMemorySize, SMEM_BYTES);

    zero_stats_kernel<<<1, C>>>();
    conv_stats_kernel<<<N_ROWS / TILE_M, NTHREADS, SMEM_BYTES>>>(
        features, nmap, weight, out);
    norm_relu_kernel<<<1184, 256>>>(out, gamma, beta);
}

// round 4
// speedup vs baseline: 4.2142x; 4.2142x over previous
#include <cuda_runtime.h>
#include <cstdint>

#define N_ROWS 400000
#define C      64
#define KTAPS  27
#define TILE_M 128
#define NTH    128          // 4 warps
#define EPS_F  1e-5f

#define FS_STR 68           // A tile row stride (floats): conflict-free A frags
#define WS_STR 72           // B tile row stride (floats): conflict-free B frags
#define SMEM_BYTES ((TILE_M * FS_STR + C * WS_STR) * 4)   // 53248

__device__ float g_sum[C];
__device__ float g_sumsq[C];

static __device__ __forceinline__ float f2tf32(float x) {
    float r;
    asm("cvt.rna.tf32.f32 %0, %1;" : "=f"(r) : "f"(x));
    return r;
}

static __device__ __forceinline__ void mma_tf32(float& c0, float& c1, float& c2, float& c3,
                                                uint32_t a0, uint32_t a1, uint32_t a2, uint32_t a3,
                                                uint32_t b0, uint32_t b1) {
    asm volatile(
        "mma.sync.aligned.m16n8k8.row.col.f32.tf32.tf32.f32 "
        "{%0,%1,%2,%3}, {%4,%5,%6,%7}, {%8,%9}, {%0,%1,%2,%3};"
        : "+f"(c0), "+f"(c1), "+f"(c2), "+f"(c3)
        : "r"(a0), "r"(a1), "r"(a2), "r"(a3), "r"(b0), "r"(b1));
}

__global__ void zero_stats_kernel() {
    int t = threadIdx.x;
    if (t < C) { g_sum[t] = 0.0f; g_sumsq[t] = 0.0f; }
}

extern __shared__ float smem[];

__global__ __launch_bounds__(NTH)
void conv_mma_kernel(const float* __restrict__ features,
                     const int*   __restrict__ nmap,
                     const float* __restrict__ weight,
                     float*       __restrict__ out)
{
    float* fs  = smem;                       // [128][FS_STR] gathered A (tf32)
    float* wsm = smem + TILE_M * FS_STR;     // [64][WS_STR]  W_k as [cin][cout] (tf32)

    const int tid  = threadIdx.x;
    const int wid  = tid >> 5;               // 0..3 : rows [wid*32, wid*32+32)
    const int lane = tid & 31;
    const int grp  = lane >> 2;              // 0..7
    const int tig  = lane & 3;               // 0..3
    const int row0 = blockIdx.x * TILE_M;

    // gather mapping: 16 threads per row, one float4 each
    const int chunk = tid & 15;
    const int r0t   = tid >> 4;              // 0..7, rows step 8

    const float4* feat4 = (const float4*)features;

    // accumulators: 2 m-tiles x 8 n-tiles x 4 frag regs
    float acc[2][8][4];
#pragma unroll
    for (int mt = 0; mt < 2; ++mt)
#pragma unroll
        for (int nt = 0; nt < 8; ++nt)
#pragma unroll
            for (int e = 0; e < 4; ++e) acc[mt][nt][e] = 0.0f;

    for (int k = 0; k < KTAPS; ++k) {
        __syncthreads();   // protect previous iteration's smem reads

        // ---- stage W_k [64 cin][64 cout] -> wsm (tf32-rounded)
        {
            const float4* wg = (const float4*)(weight + k * C * C);
#pragma unroll
            for (int u = 0; u < 8; ++u) {
                const int idx4 = tid + u * NTH;       // 0..1023
                const int j  = idx4 >> 4;             // cin row
                const int n0 = (idx4 & 15) * 4;       // cout start
                float4 v = wg[idx4];
                float* d = wsm + j * WS_STR + n0;
                d[0] = f2tf32(v.x); d[1] = f2tf32(v.y);
                d[2] = f2tf32(v.z); d[3] = f2tf32(v.w);
            }
        }

        // ---- gather 128 feature rows (tf32-rounded)
        {
            const int* nm = nmap + k * N_ROWS + row0;
#pragma unroll
            for (int i = 0; i < 16; ++i) {
                const int rr  = r0t + i * 8;
                const int idx = __ldg(nm + rr);
                float4 v = make_float4(0.f, 0.f, 0.f, 0.f);
                if (idx >= 0) v = __ldg(&feat4[(size_t)idx * 16 + chunk]);
                float* d = fs + rr * FS_STR + chunk * 4;
                d[0] = f2tf32(v.x); d[1] = f2tf32(v.y);
                d[2] = f2tf32(v.z); d[3] = f2tf32(v.w);
            }
        }
        __syncthreads();

        // ---- 8 k-steps of m16n8k8 tf32 mma
        const int rb0 = wid * 32;
#pragma unroll
        for (int k0 = 0; k0 < 8; ++k0) {
            const int kc = k0 * 8;
            uint32_t a[2][4];
#pragma unroll
            for (int mt = 0; mt < 2; ++mt) {
                const float* ar = fs + (rb0 + mt * 16 + grp) * FS_STR + kc;
                a[mt][0] = __float_as_uint(ar[tig]);
                a[mt][1] = __float_as_uint(ar[8 * FS_STR + tig]);
                a[mt][2] = __float_as_uint(ar[tig + 4]);
                a[mt][3] = __float_as_uint(ar[8 * FS_STR + tig + 4]);
            }
            const float* br = wsm + kc * WS_STR + grp;
#pragma unroll
            for (int nt = 0; nt < 8; ++nt) {
                uint32_t b0 = __float_as_uint(br[tig * WS_STR + nt * 8]);
                uint32_t b1 = __float_as_uint(br[(tig + 4) * WS_STR + nt * 8]);
                mma_tf32(acc[0][nt][0], acc[0][nt][1], acc[0][nt][2], acc[0][nt][3],
                         a[0][0], a[0][1], a[0][2], a[0][3], b0, b1);
                mma_tf32(acc[1][nt][0], acc[1][nt][1], acc[1][nt][2], acc[1][nt][3],
                         a[1][0], a[1][1], a[1][2], a[1][3], b0, b1);
            }
        }
    }

    // ---- epilogue: write conv output (pre-norm)
#pragma unroll
    for (int mt = 0; mt < 2; ++mt) {
        const int r = row0 + wid * 32 + mt * 16 + grp;
#pragma unroll
        for (int nt = 0; nt < 8; ++nt) {
            const int cpos = nt * 8 + tig * 2;
            *(float2*)(out + (size_t)r * C + cpos) =
                make_float2(acc[mt][nt][0], acc[mt][nt][1]);
            *(float2*)(out + (size_t)(r + 8) * C + cpos) =
                make_float2(acc[mt][nt][2], acc[mt][nt][3]);
        }
    }
}

__global__ __launch_bounds__(256)
void stats_kernel(const float* __restrict__ out)
{
    __shared__ float ss[256], qq[256];
    const int tid = threadIdx.x;
    const int c = tid & 63;
    const int g = tid >> 6;
    float s = 0.f, q = 0.f;
    for (int row = blockIdx.x * 4 + g; row < N_ROWS; row += gridDim.x * 4) {
        float v = out[(size_t)row * C + c];
        s += v; q += v * v;
    }
    ss[tid] = s; qq[tid] = q;
    __syncthreads();
    if (tid < C) {
        float S = ss[tid] + ss[tid + 64] + ss[tid + 128] + ss[tid + 192];
        float Q = qq[tid] + qq[tid + 64] + qq[tid + 128] + qq[tid + 192];
        atomicAdd(&g_sum[tid], S);
        atomicAdd(&g_sumsq[tid], Q);
    }
}

__global__ __launch_bounds__(256)
void norm_relu_kernel(float* __restrict__ out,
                      const float* __restrict__ gamma,
                      const float* __restrict__ beta)
{
    __shared__ float sc[C], sh[C];
    int t = threadIdx.x;
    if (t < C) {
        const float invn = 1.0f / (float)N_ROWS;
        float mean = g_sum[t] * invn;
        float var  = g_sumsq[t] * invn - mean * mean;
        float inv  = rsqrtf(var + EPS_F);
        float g    = gamma[t] * inv;
        sc[t] = g;
        sh[t] = beta[t] - mean * g;
    }
    __syncthreads();

    const int total4 = N_ROWS * C / 4;
    float4* o4 = (float4*)out;
    for (int i = blockIdx.x * blockDim.x + t; i < total4;
         i += gridDim.x * blockDim.x) {
        float4 v = o4[i];
        int cb = (i & 15) * 4;
        v.x = fmaxf(fmaf(v.x, sc[cb + 0], sh[cb + 0]), 0.0f);
        v.y = fmaxf(fmaf(v.y, sc[cb + 1], sh[cb + 1]), 0.0f);
        v.z = fmaxf(fmaf(v.z, sc[cb + 2], sh[cb + 2]), 0.0f);
        v.w = fmaxf(fmaf(v.w, sc[cb + 3], sh[cb + 3]), 0.0f);
        o4[i] = v;
    }
}

extern "C" void kernel_launch(void* const* d_in, const int* in_sizes, int n_in,
                              void* d_out, int out_size)
{
    const float* features = (const float*)d_in[0];
    const int*   nmap     = (const int*)  d_in[1];
    const float* weight   = (const float*)d_in[2];
    const float* gamma    = (const float*)d_in[3];
    const float* beta     = (const float*)d_in[4];
    float* out = (float*)d_out;

    cudaFuncSetAttribute(conv_mma_kernel,
                         cudaFuncAttributeMaxDynamicSharedMemorySize, SMEM_BYTES);

    zero_stats_kernel<<<1, C>>>();
    conv_mma_kernel<<<N_ROWS / TILE_M, NTH, SMEM_BYTES>>>(features, nmap, weight, out);
    stats_kernel<<<1024, 256>>>(out);
    norm_relu_kernel<<<1184, 256>>>(out, gamma, beta);
}

// round 8
// speedup vs baseline: 4.5165x; 1.0717x over previous
#include <cuda_runtime.h>
#include <cstdint>

#define N_ROWS 400000
#define C      64
#define KTAPS  27
#define TILE_M 128
#define NTH    128          // 4 warps
#define EPS_F  1e-5f

#define FS_STR 68           // A row stride (floats): conflict-free A frags
#define WS_STR 72           // B row stride (floats): conflict-free B frags
#define ASZ_F  (TILE_M * FS_STR)       // floats per A buffer (8704)
#define BSZ_F  (C * WS_STR)            // floats per B buffer (4608)
#define BBASE_BYTES (2 * ASZ_F * 4)    // B buffers start after 2 A buffers
#define SMEM_BYTES ((2 * ASZ_F + 2 * BSZ_F) * 4)   // 106496

__device__ float g_sum[C];
__device__ float g_sumsq[C];

// ---------------- helpers ----------------
static __device__ __forceinline__ uint32_t smem_u32(const void* p) {
    uint32_t a;
    asm("{ .reg .u64 t; cvta.to.shared.u64 t, %1; cvt.u32.u64 %0, t; }"
        : "=r"(a) : "l"(p));
    return a;
}

static __device__ __forceinline__ float f2tf32(float x) {
    float r;
    asm("cvt.rna.tf32.f32 %0, %1;" : "=f"(r) : "f"(x));
    return r;
}

static __device__ __forceinline__ uint32_t ldcvt(const float* p) {
    return __float_as_uint(f2tf32(*p));
}

static __device__ __forceinline__ void cp16(uint32_t dst, const void* src,
                                            uint32_t src_bytes) {
    asm volatile("cp.async.cg.shared.global [%0], [%1], 16, %2;"
                 :: "r"(dst), "l"(src), "r"(src_bytes) : "memory");
}
#define CP_COMMIT() asm volatile("cp.async.commit_group;" ::: "memory")
#define CP_WAIT(n)  asm volatile("cp.async.wait_group %0;" :: "n"(n) : "memory")

static __device__ __forceinline__ void mma_tf32(float& c0, float& c1, float& c2, float& c3,
                                                uint32_t a0, uint32_t a1, uint32_t a2, uint32_t a3,
                                                uint32_t b0, uint32_t b1) {
    asm volatile(
        "mma.sync.aligned.m16n8k8.row.col.f32.tf32.tf32.f32 "
        "{%0,%1,%2,%3}, {%4,%5,%6,%7}, {%8,%9}, {%0,%1,%2,%3};"
        : "+f"(c0), "+f"(c1), "+f"(c2), "+f"(c3)
        : "r"(a0), "r"(a1), "r"(a2), "r"(a3), "r"(b0), "r"(b1));
}

__global__ void zero_stats_kernel() {
    int t = threadIdx.x;
    if (t < C) { g_sum[t] = 0.0f; g_sumsq[t] = 0.0f; }
}

extern __shared__ float smem[];

__global__ __launch_bounds__(NTH)
void conv_mma_kernel(const float* __restrict__ features,
                     const int*   __restrict__ nmap,
                     const float* __restrict__ weight,
                     float*       __restrict__ out)
{
    const uint32_t sb = smem_u32(smem);
    const int tid  = threadIdx.x;
    const int wid  = tid >> 5;
    const int lane = tid & 31;
    const int grp  = lane >> 2;              // 0..7
    const int tig  = lane & 3;               // 0..3
    const int row0 = blockIdx.x * TILE_M;

    const int chunk = tid & 15;              // float4 within a 64-float row
    const int r0t   = tid >> 4;              // rows r0t, r0t+8, ... (16 rows)

    const float4* feat4 = (const float4*)features;
    const float4* wg4   = (const float4*)weight;

    float acc[2][8][4];
#pragma unroll
    for (int mt = 0; mt < 2; ++mt)
#pragma unroll
        for (int nt = 0; nt < 8; ++nt)
#pragma unroll
            for (int e = 0; e < 4; ++e) acc[mt][nt][e] = 0.0f;

    int idx_nx[16];

    // ---- issue staging for a tap into buffer bs (A uses given idx array) ----
    auto issue_tap = [&](int t, int bs, const int* idxv) {
        // B: W_t [64 cin][64 cout] raw fp32
        const uint32_t bdst0 = sb + BBASE_BYTES + bs * (BSZ_F * 4);
#pragma unroll
        for (int u = 0; u < 8; ++u) {
            const int idx4 = tid + u * NTH;            // 0..1023
            const int j  = idx4 >> 4;
            const int c4 = idx4 & 15;
            cp16(bdst0 + j * (WS_STR * 4) + c4 * 16, wg4 + t * 1024 + idx4, 16);
        }
        // A: gather 128 feature rows raw fp32 (zfill for holes)
        const uint32_t adst0 = sb + bs * (ASZ_F * 4);
#pragma unroll
        for (int i = 0; i < 16; ++i) {
            const int rr  = r0t + i * 8;
            const int idx = idxv[i];
            const int safe = idx < 0 ? 0 : idx;
            cp16(adst0 + rr * (FS_STR * 4) + chunk * 16,
                 feat4 + (size_t)safe * 16 + chunk, idx < 0 ? 0u : 16u);
        }
        CP_COMMIT();
    };

    // ---- prologue: stage tap 0, prefetch idx for tap 1 ----
    {
        int idx0[16];
        const int* nm = nmap + 0 * N_ROWS + row0;
#pragma unroll
        for (int i = 0; i < 16; ++i) idx0[i] = __ldg(nm + r0t + i * 8);
        issue_tap(0, 0, idx0);
        const int* nm1 = nmap + 1 * N_ROWS + row0;
#pragma unroll
        for (int i = 0; i < 16; ++i) idx_nx[i] = __ldg(nm1 + r0t + i * 8);
    }

    for (int k = 0; k < KTAPS; ++k) {
        const int s = k & 1;

        if (k + 1 < KTAPS) {
            issue_tap(k + 1, s ^ 1, idx_nx);
            if (k + 2 < KTAPS) {
                const int* nm = nmap + (k + 2) * N_ROWS + row0;
#pragma unroll
                for (int i = 0; i < 16; ++i) idx_nx[i] = __ldg(nm + r0t + i * 8);
            }
            CP_WAIT(1);          // buffer s complete (only k+1's group may remain)
        } else {
            CP_WAIT(0);
        }
        __syncthreads();         // all threads' copies visible

        // ---- compute tap k on buffer s ----
        const float* fs  = smem + s * ASZ_F;
        const float* wsm = smem + 2 * ASZ_F + s * BSZ_F;
        const int rb0 = wid * 32;
#pragma unroll
        for (int k0 = 0; k0 < 8; ++k0) {
            const int kc = k0 * 8;
            uint32_t a[2][4];
#pragma unroll
            for (int mt = 0; mt < 2; ++mt) {
                const float* ar = fs + (rb0 + mt * 16 + grp) * FS_STR + kc;
                a[mt][0] = ldcvt(ar + tig);
                a[mt][1] = ldcvt(ar + 8 * FS_STR + tig);
                a[mt][2] = ldcvt(ar + tig + 4);
                a[mt][3] = ldcvt(ar + 8 * FS_STR + tig + 4);
            }
            const float* br = wsm + kc * WS_STR + grp;
#pragma unroll
            for (int nt = 0; nt < 8; ++nt) {
                uint32_t b0 = ldcvt(br + tig * WS_STR + nt * 8);
                uint32_t b1 = ldcvt(br + (tig + 4) * WS_STR + nt * 8);
                mma_tf32(acc[0][nt][0], acc[0][nt][1], acc[0][nt][2], acc[0][nt][3],
                         a[0][0], a[0][1], a[0][2], a[0][3], b0, b1);
                mma_tf32(acc[1][nt][0], acc[1][nt][1], acc[1][nt][2], acc[1][nt][3],
                         a[1][0], a[1][1], a[1][2], a[1][3], b0, b1);
            }
        }
        __syncthreads();         // buffer s may be overwritten next iteration
    }

    // ---- epilogue: write conv output (pre-norm) ----
#pragma unroll
    for (int mt = 0; mt < 2; ++mt) {
        const int r = row0 + wid * 32 + mt * 16 + grp;
#pragma unroll
        for (int nt = 0; nt < 8; ++nt) {
            const int cpos = nt * 8 + tig * 2;
            *(float2*)(out + (size_t)r * C + cpos) =
                make_float2(acc[mt][nt][0], acc[mt][nt][1]);
            *(float2*)(out + (size_t)(r + 8) * C + cpos) =
                make_float2(acc[mt][nt][2], acc[mt][nt][3]);
        }
    }
}

__global__ __launch_bounds__(256)
void stats_kernel(const float* __restrict__ out)
{
    __shared__ float ss[256], qq[256];
    const int tid = threadIdx.x;
    const int c = tid & 63;
    const int g = tid >> 6;
    float s = 0.f, q = 0.f;
    for (int row = blockIdx.x * 4 + g; row < N_ROWS; row += gridDim.x * 4) {
        float v = out[(size_t)row * C + c];
        s += v; q += v * v;
    }
    ss[tid] = s; qq[tid] = q;
    __syncthreads();
    if (tid < C) {
        float S = ss[tid] + ss[tid + 64] + ss[tid + 128] + ss[tid + 192];
        float Q = qq[tid] + qq[tid + 64] + qq[tid + 128] + qq[tid + 192];
        atomicAdd(&g_sum[tid], S);
        atomicAdd(&g_sumsq[tid], Q);
    }
}

__global__ __launch_bounds__(256)
void norm_relu_kernel(float* __restrict__ out,
                      const float* __restrict__ gamma,
                      const float* __restrict__ beta)
{
    __shared__ float sc[C], sh[C];
    int t = threadIdx.x;
    if (t < C) {
        const float invn = 1.0f / (float)N_ROWS;
        float mean = g_sum[t] * invn;
        float var  = g_sumsq[t] * invn - mean * mean;
        float inv  = rsqrtf(var + EPS_F);
        float g    = gamma[t] * inv;
        sc[t] = g;
        sh[t] = beta[t] - mean * g;
    }
    __syncthreads();

    const int total4 = N_ROWS * C / 4;
    float4* o4 = (float4*)out;
    for (int i = blockIdx.x * blockDim.x + t; i < total4;
         i += gridDim.x * blockDim.x) {
        float4 v = o4[i];
        int cb = (i & 15) * 4;
        v.x = fmaxf(fmaf(v.x, sc[cb + 0], sh[cb + 0]), 0.0f);
        v.y = fmaxf(fmaf(v.y, sc[cb + 1], sh[cb + 1]), 0.0f);
        v.z = fmaxf(fmaf(v.z, sc[cb + 2], sh[cb + 2]), 0.0f);
        v.w = fmaxf(fmaf(v.w, sc[cb + 3], sh[cb + 3]), 0.0f);
        o4[i] = v;
    }
}

extern "C" void kernel_launch(void* const* d_in, const int* in_sizes, int n_in,
                              void* d_out, int out_size)
{
    const float* features = (const float*)d_in[0];
    const int*   nmap     = (const int*)  d_in[1];
    const float* weight   = (const float*)d_in[2];
    const float* gamma    = (const float*)d_in[3];
    const float* beta     = (const float*)d_in[4];
    float* out = (float*)d_out;

    cudaFuncSetAttribute(conv_mma_kernel,
                         cudaFuncAttributeMaxDynamicSharedMemorySize, SMEM_BYTES);

    zero_stats_kernel<<<1, C>>>();
    conv_mma_kernel<<<N_ROWS / TILE_M, NTH, SMEM_BYTES>>>(features, nmap, weight, out);
    stats_kernel<<<1024, 256>>>(out);
    norm_relu_kernel<<<1184, 256>>>(out, gamma, beta);
}

// round 9
// speedup vs baseline: 4.8323x; 1.0699x over previous
#include <cuda_runtime.h>
#include <cstdint>

#define N_ROWS 400000
#define C      64
#define KTAPS  27
#define TILE_M 128
#define NTH    64           // 2 warps, each owns a 64x64 output tile
#define EPS_F  1e-5f

#define FS_STR 68           // A row stride (floats): banks 4*grp+tig all distinct
#define WS_STR 72           // B row stride (floats): banks 8*tig+grp all distinct
#define ASZ_F  (TILE_M * FS_STR)       // 8704
#define BSZ_F  (C * WS_STR)            // 4608
#define BBASE_BYTES (2 * ASZ_F * 4)
#define SMEM_BYTES ((2 * ASZ_F + 2 * BSZ_F) * 4)   // 106496 -> 2 blocks/SM

__device__ float g_sum[C];
__device__ float g_sumsq[C];
__device__ float g_featr[(size_t)N_ROWS * C];   // tf32-pre-rounded features
__device__ float g_wr[KTAPS * C * C];           // tf32-pre-rounded weights

// ---------------- helpers ----------------
static __device__ __forceinline__ uint32_t smem_u32(const void* p) {
    uint32_t a;
    asm("{ .reg .u64 t; cvta.to.shared.u64 t, %1; cvt.u32.u64 %0, t; }"
        : "=r"(a) : "l"(p));
    return a;
}
static __device__ __forceinline__ float f2tf32(float x) {
    float r;
    asm("cvt.rna.tf32.f32 %0, %1;" : "=f"(r) : "f"(x));
    return r;
}
static __device__ __forceinline__ void cp16(uint32_t dst, const void* src,
                                            uint32_t src_bytes) {
    asm volatile("cp.async.cg.shared.global [%0], [%1], 16, %2;"
                 :: "r"(dst), "l"(src), "r"(src_bytes) : "memory");
}
#define CP_COMMIT() asm volatile("cp.async.commit_group;" ::: "memory")
#define CP_WAIT(n)  asm volatile("cp.async.wait_group %0;" :: "n"(n) : "memory")

static __device__ __forceinline__ void mma_tf32(float& c0, float& c1, float& c2, float& c3,
                                                uint32_t a0, uint32_t a1, uint32_t a2, uint32_t a3,
                                                uint32_t b0, uint32_t b1) {
    asm volatile(
        "mma.sync.aligned.m16n8k8.row.col.f32.tf32.tf32.f32 "
        "{%0,%1,%2,%3}, {%4,%5,%6,%7}, {%8,%9}, {%0,%1,%2,%3};"
        : "+f"(c0), "+f"(c1), "+f"(c2), "+f"(c3)
        : "r"(a0), "r"(a1), "r"(a2), "r"(a3), "r"(b0), "r"(b1));
}

// ---------------- prep kernels ----------------
__global__ __launch_bounds__(256)
void prep_w_kernel(const float* __restrict__ w) {
    int i = blockIdx.x * 256 + threadIdx.x;
    if (i < KTAPS * C * C) g_wr[i] = f2tf32(w[i]);
    if (blockIdx.x == 0 && threadIdx.x < C) {
        g_sum[threadIdx.x] = 0.0f; g_sumsq[threadIdx.x] = 0.0f;
    }
}

__global__ __launch_bounds__(256)
void prep_f_kernel(const float4* __restrict__ f) {
    int i = blockIdx.x * 256 + threadIdx.x;        // 6.4M float4
    float4 v = f[i];
    v.x = f2tf32(v.x); v.y = f2tf32(v.y); v.z = f2tf32(v.z); v.w = f2tf32(v.w);
    ((float4*)g_featr)[i] = v;
}

// ---------------- conv kernel ----------------
extern __shared__ float smem[];

__global__ __launch_bounds__(NTH)
void conv_mma_kernel(const int* __restrict__ nmap,
                     float*     __restrict__ out)
{
    const uint32_t sb = smem_u32(smem);
    const int tid  = threadIdx.x;
    const int wid  = tid >> 5;               // 0..1
    const int lane = tid & 31;
    const int grp  = lane >> 2;              // 0..7
    const int tig  = lane & 3;               // 0..3
    const int row0 = blockIdx.x * TILE_M;
    const int rb0  = wid * 64;               // warp's 64-row slab

    const int chunk = tid & 15;              // float4 within a 64-float row
    const int r0t   = tid >> 4;              // 0..3; rows r0t + 4i

    const float4* feat4 = (const float4*)g_featr;
    const float4* wg4   = (const float4*)g_wr;

    float acc[4][8][4];
#pragma unroll
    for (int mt = 0; mt < 4; ++mt)
#pragma unroll
        for (int nt = 0; nt < 8; ++nt)
#pragma unroll
            for (int e = 0; e < 4; ++e) acc[mt][nt][e] = 0.0f;

    int idx_nx[32];

    auto issue_tap = [&](int t, int bs, const int* idxv) {
        // B: 64x64 floats = 1024 float4 over 64 threads -> 16 cp16/thread
        const uint32_t bdst0 = sb + BBASE_BYTES + bs * (BSZ_F * 4);
#pragma unroll
        for (int u = 0; u < 16; ++u) {
            const int idx4 = tid + u * NTH;
            const int j  = idx4 >> 4;
            const int c4 = idx4 & 15;
            cp16(bdst0 + j * (WS_STR * 4) + c4 * 16, wg4 + t * 1024 + idx4, 16);
        }
        // A: 128 rows x 16 float4 over 64 threads -> 32 cp16/thread
        const uint32_t adst0 = sb + bs * (ASZ_F * 4);
#pragma unroll
        for (int i = 0; i < 32; ++i) {
            const int rr  = r0t + i * 4;
            const int idx = idxv[i];
            const int safe = idx < 0 ? 0 : idx;
            cp16(adst0 + rr * (FS_STR * 4) + chunk * 16,
                 feat4 + (size_t)safe * 16 + chunk, idx < 0 ? 0u : 16u);
        }
        CP_COMMIT();
    };

    // prologue
    {
        int idx0[32];
        const int* nm = nmap + row0;
#pragma unroll
        for (int i = 0; i < 32; ++i) idx0[i] = __ldg(nm + r0t + i * 4);
        issue_tap(0, 0, idx0);
        const int* nm1 = nmap + N_ROWS + row0;
#pragma unroll
        for (int i = 0; i < 32; ++i) idx_nx[i] = __ldg(nm1 + r0t + i * 4);
    }

    for (int k = 0; k < KTAPS; ++k) {
        const int s = k & 1;

        if (k + 1 < KTAPS) {
            issue_tap(k + 1, s ^ 1, idx_nx);
            if (k + 2 < KTAPS) {
                const int* nm = nmap + (k + 2) * N_ROWS + row0;
#pragma unroll
                for (int i = 0; i < 32; ++i) idx_nx[i] = __ldg(nm + r0t + i * 4);
            }
            CP_WAIT(1);
        } else {
            CP_WAIT(0);
        }
        __syncthreads();

        const uint32_t* fs  = (const uint32_t*)(smem + s * ASZ_F);
        const uint32_t* wsm = (const uint32_t*)(smem + 2 * ASZ_F + s * BSZ_F);

#pragma unroll
        for (int k0 = 0; k0 < 8; ++k0) {
            const int kc = k0 * 8;
            uint32_t a[4][4];
#pragma unroll
            for (int mt = 0; mt < 4; ++mt) {
                const uint32_t* ar = fs + (rb0 + mt * 16 + grp) * FS_STR + kc;
                a[mt][0] = ar[tig];
                a[mt][1] = ar[8 * FS_STR + tig];
                a[mt][2] = ar[tig + 4];
                a[mt][3] = ar[8 * FS_STR + tig + 4];
            }
            const uint32_t* br = wsm + kc * WS_STR + grp;
#pragma unroll
            for (int nt = 0; nt < 8; ++nt) {
                uint32_t b0 = br[tig * WS_STR + nt * 8];
                uint32_t b1 = br[(tig + 4) * WS_STR + nt * 8];
#pragma unroll
                for (int mt = 0; mt < 4; ++mt)
                    mma_tf32(acc[mt][nt][0], acc[mt][nt][1],
                             acc[mt][nt][2], acc[mt][nt][3],
                             a[mt][0], a[mt][1], a[mt][2], a[mt][3], b0, b1);
            }
        }
        __syncthreads();
    }

    // ---- epilogue: store conv output + fused channel stats ----
#pragma unroll
    for (int mt = 0; mt < 4; ++mt) {
        const int r = row0 + rb0 + mt * 16 + grp;
#pragma unroll
        for (int nt = 0; nt < 8; ++nt) {
            const int cpos = nt * 8 + tig * 2;
            *(float2*)(out + (size_t)r * C + cpos) =
                make_float2(acc[mt][nt][0], acc[mt][nt][1]);
            *(float2*)(out + (size_t)(r + 8) * C + cpos) =
                make_float2(acc[mt][nt][2], acc[mt][nt][3]);
        }
    }

    // per-channel sum / sumsq: reduce over the 8 grp-lanes, lanes 0-3 emit atomics
#pragma unroll
    for (int nt = 0; nt < 8; ++nt) {
        float s0 = 0.f, s1 = 0.f, q0 = 0.f, q1 = 0.f;
#pragma unroll
        for (int mt = 0; mt < 4; ++mt) {
            s0 += acc[mt][nt][0] + acc[mt][nt][2];
            s1 += acc[mt][nt][1] + acc[mt][nt][3];
            q0 += acc[mt][nt][0] * acc[mt][nt][0] + acc[mt][nt][2] * acc[mt][nt][2];
            q1 += acc[mt][nt][1] * acc[mt][nt][1] + acc[mt][nt][3] * acc[mt][nt][3];
        }
#pragma unroll
        for (int d = 4; d <= 16; d <<= 1) {      // reduce over grp bits (lane bits 2..4)
            s0 += __shfl_xor_sync(0xFFFFFFFF, s0, d);
            s1 += __shfl_xor_sync(0xFFFFFFFF, s1, d);
            q0 += __shfl_xor_sync(0xFFFFFFFF, q0, d);
            q1 += __shfl_xor_sync(0xFFFFFFFF, q1, d);
        }
        if (lane < 4) {
            const int ch = nt * 8 + lane * 2;
            atomicAdd(&g_sum[ch],     s0);
            atomicAdd(&g_sum[ch + 1], s1);
            atomicAdd(&g_sumsq[ch],     q0);
            atomicAdd(&g_sumsq[ch + 1], q1);
        }
    }
}

__global__ __launch_bounds__(256)
void norm_relu_kernel(float* __restrict__ out,
                      const float* __restrict__ gamma,
                      const float* __restrict__ beta)
{
    __shared__ float sc[C], sh[C];
    int t = threadIdx.x;
    if (t < C) {
        const float invn = 1.0f / (float)N_ROWS;
        float mean = g_sum[t] * invn;
        float var  = g_sumsq[t] * invn - mean * mean;
        float inv  = rsqrtf(var + EPS_F);
        float g    = gamma[t] * inv;
        sc[t] = g;
        sh[t] = beta[t] - mean * g;
    }
    __syncthreads();

    const int total4 = N_ROWS * C / 4;
    float4* o4 = (float4*)out;
    for (int i = blockIdx.x * blockDim.x + t; i < total4;
         i += gridDim.x * blockDim.x) {
        float4 v = o4[i];
        int cb = (i & 15) * 4;
        v.x = fmaxf(fmaf(v.x, sc[cb + 0], sh[cb + 0]), 0.0f);
        v.y = fmaxf(fmaf(v.y, sc[cb + 1], sh[cb + 1]), 0.0f);
        v.z = fmaxf(fmaf(v.z, sc[cb + 2], sh[cb + 2]), 0.0f);
        v.w = fmaxf(fmaf(v.w, sc[cb + 3], sh[cb + 3]), 0.0f);
        o4[i] = v;
    }
}

extern "C" void kernel_launch(void* const* d_in, const int* in_sizes, int n_in,
                              void* d_out, int out_size)
{
    const float* features = (const float*)d_in[0];
    const int*   nmap     = (const int*)  d_in[1];
    const float* weight   = (const float*)d_in[2];
    const float* gamma    = (const float*)d_in[3];
    const float* beta     = (const float*)d_in[4];
    float* out = (float*)d_out;

    cudaFuncSetAttribute(conv_mma_kernel,
                         cudaFuncAttributeMaxDynamicSharedMemorySize, SMEM_BYTES);

    prep_w_kernel<<<(KTAPS * C * C + 255) / 256, 256>>>(weight);
    prep_f_kernel<<<N_ROWS * C / 4 / 256, 256>>>((const float4*)features);
    conv_mma_kernel<<<N_ROWS / TILE_M, NTH, SMEM_BYTES>>>(nmap, out);
    norm_relu_kernel<<<1184, 256>>>(out, gamma, beta);
}

// round 12
// speedup vs baseline: 9.3278x; 1.9303x over previous
#include <cuda_runtime.h>
#include <cuda_fp16.h>
#include <cstdint>

#define N_ROWS 400000
#define C      64
#define KTAPS  27
#define TILE_M 128
#define NTH    64           // 2 warps, each owns a 64x64 output tile
#define EPS_F  1e-5f

#define STRH   72                         // smem row stride in halves (144 B)
#define ABUF_B (TILE_M * STRH * 2)        // 18432 B per A buffer
#define BBUF_B (C * STRH * 2)             // 9216 B per B buffer
#define BBASE  (2 * ABUF_B)               // B buffers after both A buffers
#define SMEM_BYTES (2 * ABUF_B + 2 * BBUF_B)   // 55296 -> 4 blocks/SM

__device__ float g_sum[C];
__device__ float g_sumsq[C];
__device__ __align__(16) __half g_fh[(size_t)N_ROWS * C];   // fp16 features
__device__ __align__(16) __half g_wh[KTAPS * C * C];        // fp16 W^T [tap][cout][cin]

// ---------------- helpers ----------------
static __device__ __forceinline__ uint32_t smem_u32(const void* p) {
    uint32_t a;
    asm("{ .reg .u64 t; cvta.to.shared.u64 t, %1; cvt.u32.u64 %0, t; }"
        : "=r"(a) : "l"(p));
    return a;
}
static __device__ __forceinline__ uint32_t h2_bits(__half2 h) {
    return *reinterpret_cast<uint32_t*>(&h);
}
static __device__ __forceinline__ void cp16(uint32_t dst, const void* src,
                                            uint32_t src_bytes) {
    asm volatile("cp.async.cg.shared.global [%0], [%1], 16, %2;"
                 :: "r"(dst), "l"(src), "r"(src_bytes) : "memory");
}
#define CP_COMMIT() asm volatile("cp.async.commit_group;" ::: "memory")
#define CP_WAIT(n)  asm volatile("cp.async.wait_group %0;" :: "n"(n) : "memory")

static __device__ __forceinline__ void mma_f16(float& c0, float& c1, float& c2, float& c3,
                                               uint32_t a0, uint32_t a1, uint32_t a2, uint32_t a3,
                                               uint32_t b0, uint32_t b1) {
    asm volatile(
        "mma.sync.aligned.m16n8k16.row.col.f32.f16.f16.f32 "
        "{%0,%1,%2,%3}, {%4,%5,%6,%7}, {%8,%9}, {%0,%1,%2,%3};"
        : "+f"(c0), "+f"(c1), "+f"(c2), "+f"(c3)
        : "r"(a0), "r"(a1), "r"(a2), "r"(a3), "r"(b0), "r"(b1));
}

// ---------------- prep kernels ----------------
__global__ __launch_bounds__(256)
void prep_w_kernel(const float* __restrict__ w) {
    int i = blockIdx.x * 256 + threadIdx.x;
    if (i < KTAPS * C * C) {
        int t = i >> 12;             // tap
        int j = (i >> 6) & 63;       // cin
        int n = i & 63;              // cout
        g_wh[(t << 12) + (n << 6) + j] = __float2half_rn(w[i]);
    }
    if (blockIdx.x == 0 && threadIdx.x < C) {
        g_sum[threadIdx.x] = 0.0f; g_sumsq[threadIdx.x] = 0.0f;
    }
}

__global__ __launch_bounds__(256)
void prep_f_kernel(const float4* __restrict__ f) {
    int i = blockIdx.x * 256 + threadIdx.x;        // over 3.2M uint4-halves
    float4 v0 = f[2 * i];
    float4 v1 = f[2 * i + 1];
    uint4 o;
    o.x = h2_bits(__float22half2_rn(make_float2(v0.x, v0.y)));
    o.y = h2_bits(__float22half2_rn(make_float2(v0.z, v0.w)));
    o.z = h2_bits(__float22half2_rn(make_float2(v1.x, v1.y)));
    o.w = h2_bits(__float22half2_rn(make_float2(v1.z, v1.w)));
    ((uint4*)g_fh)[i] = o;
}

// ---------------- conv kernel ----------------
extern __shared__ __align__(16) char smem[];

__global__ __launch_bounds__(NTH)
void conv_mma_kernel(const int* __restrict__ nmap,
                     float*     __restrict__ out)
{
    const uint32_t sb = smem_u32(smem);
    const int tid  = threadIdx.x;
    const int wid  = tid >> 5;               // 0..1
    const int lane = tid & 31;
    const int grp  = lane >> 2;              // 0..7
    const int tig  = lane & 3;               // 0..3
    const int row0 = blockIdx.x * TILE_M;
    const int rb0  = wid * 64;               // warp's 64-row slab

    const int chunk = tid & 7;               // 16B chunk within a 128B fp16 row
    const int r0t   = tid >> 3;              // 0..7; rows r0t + 8i

    const uint4* feat = (const uint4*)g_fh;  // 8 uint4 per feature row
    const uint4* wgt  = (const uint4*)g_wh;  // 512 uint4 per tap

    float acc[4][8][4];
#pragma unroll
    for (int mt = 0; mt < 4; ++mt)
#pragma unroll
        for (int nt = 0; nt < 8; ++nt)
#pragma unroll
            for (int e = 0; e < 4; ++e) acc[mt][nt][e] = 0.0f;

    int idx_nx[16];

    auto issue_tap = [&](int t, int bs, const int* idxv) {
        // B: 64 rows (cout) x 128 B -> 512 cp16 over 64 threads = 8 each
        const uint32_t bdst0 = sb + BBASE + bs * BBUF_B;
#pragma unroll
        for (int u = 0; u < 8; ++u) {
            const int idx4 = tid + u * NTH;      // 0..511
            const int j  = idx4 >> 3;            // cout row
            const int c4 = idx4 & 7;
            cp16(bdst0 + j * (STRH * 2) + c4 * 16, wgt + (t << 9) + idx4, 16);
        }
        // A: 128 rows x 8 chunks -> 1024 cp16 over 64 threads = 16 each
        const uint32_t adst0 = sb + bs * ABUF_B;
#pragma unroll
        for (int i = 0; i < 16; ++i) {
            const int rr  = r0t + i * 8;
            const int idx = idxv[i];
            const int safe = idx < 0 ? 0 : idx;
            cp16(adst0 + rr * (STRH * 2) + chunk * 16,
                 feat + (size_t)safe * 8 + chunk, idx < 0 ? 0u : 16u);
        }
        CP_COMMIT();
    };

    // prologue
    {
        int idx0[16];
        const int* nm = nmap + row0;
#pragma unroll
        for (int i = 0; i < 16; ++i) idx0[i] = __ldg(nm + r0t + i * 8);
        issue_tap(0, 0, idx0);
        const int* nm1 = nmap + N_ROWS + row0;
#pragma unroll
        for (int i = 0; i < 16; ++i) idx_nx[i] = __ldg(nm1 + r0t + i * 8);
    }

    for (int k = 0; k < KTAPS; ++k) {
        const int s = k & 1;

        if (k + 1 < KTAPS) {
            issue_tap(k + 1, s ^ 1, idx_nx);
            if (k + 2 < KTAPS) {
                const int* nm = nmap + (k + 2) * N_ROWS + row0;
#pragma unroll
                for (int i = 0; i < 16; ++i) idx_nx[i] = __ldg(nm + r0t + i * 8);
            }
            CP_WAIT(1);
        } else {
            CP_WAIT(0);
        }
        __syncthreads();

        // u32 views: 36 words per smem row
        const uint32_t* fsw = (const uint32_t*)(smem + s * ABUF_B);
        const uint32_t* wsw = (const uint32_t*)(smem + BBASE + s * BBUF_B);

#pragma unroll
        for (int k0 = 0; k0 < 4; ++k0) {       // 4 k-steps of k16
            const int kw = k0 * 8;             // word offset within row
            uint32_t a[4][4];
#pragma unroll
            for (int mt = 0; mt < 4; ++mt) {
                const uint32_t* ar = fsw + (rb0 + mt * 16 + grp) * 36 + kw + tig;
                a[mt][0] = ar[0];
                a[mt][1] = ar[8 * 36];
                a[mt][2] = ar[4];
                a[mt][3] = ar[8 * 36 + 4];
            }
#pragma unroll
            for (int nt = 0; nt < 8; ++nt) {
                const uint32_t* br = wsw + (nt * 8 + grp) * 36 + kw + tig;
                uint32_t b0 = br[0];
                uint32_t b1 = br[4];
#pragma unroll
                for (int mt = 0; mt < 4; ++mt)
                    mma_f16(acc[mt][nt][0], acc[mt][nt][1],
                            acc[mt][nt][2], acc[mt][nt][3],
                            a[mt][0], a[mt][1], a[mt][2], a[mt][3], b0, b1);
            }
        }
        __syncthreads();
    }

    // ---- epilogue: store conv output + fused channel stats ----
#pragma unroll
    for (int mt = 0; mt < 4; ++mt) {
        const int r = row0 + rb0 + mt * 16 + grp;
#pragma unroll
        for (int nt = 0; nt < 8; ++nt) {
            const int cpos = nt * 8 + tig * 2;
            *(float2*)(out + (size_t)r * C + cpos) =
                make_float2(acc[mt][nt][0], acc[mt][nt][1]);
            *(float2*)(out + (size_t)(r + 8) * C + cpos) =
                make_float2(acc[mt][nt][2], acc[mt][nt][3]);
        }
    }

#pragma unroll
    for (int nt = 0; nt < 8; ++nt) {
        float s0 = 0.f, s1 = 0.f, q0 = 0.f, q1 = 0.f;
#pragma unroll
        for (int mt = 0; mt < 4; ++mt) {
            s0 += acc[mt][nt][0] + acc[mt][nt][2];
            s1 += acc[mt][nt][1] + acc[mt][nt][3];
            q0 += acc[mt][nt][0] * acc[mt][nt][0] + acc[mt][nt][2] * acc[mt][nt][2];
            q1 += acc[mt][nt][1] * acc[mt][nt][1] + acc[mt][nt][3] * acc[mt][nt][3];
        }
#pragma unroll
        for (int d = 4; d <= 16; d <<= 1) {
            s0 += __shfl_xor_sync(0xFFFFFFFF, s0, d);
            s1 += __shfl_xor_sync(0xFFFFFFFF, s1, d);
            q0 += __shfl_xor_sync(0xFFFFFFFF, q0, d);
            q1 += __shfl_xor_sync(0xFFFFFFFF, q1, d);
        }
        if (lane < 4) {
            const int ch = nt * 8 + lane * 2;
            atomicAdd(&g_sum[ch],     s0);
            atomicAdd(&g_sum[ch + 1], s1);
            atomicAdd(&g_sumsq[ch],     q0);
            atomicAdd(&g_sumsq[ch + 1], q1);
        }
    }
}

__global__ __launch_bounds__(256)
void norm_relu_kernel(float* __restrict__ out,
                      const float* __restrict__ gamma,
                      const float* __restrict__ beta)
{
    __shared__ float sc[C], sh[C];
    int t = threadIdx.x;
    if (t < C) {
        const float invn = 1.0f / (float)N_ROWS;
        float mean = g_sum[t] * invn;
        float var  = g_sumsq[t] * invn - mean * mean;
        float inv  = rsqrtf(var + EPS_F);
        float g    = gamma[t] * inv;
        sc[t] = g;
        sh[t] = beta[t] - mean * g;
    }
    __syncthreads();

    const int total4 = N_ROWS * C / 4;
    float4* o4 = (float4*)out;
    for (int i = blockIdx.x * blockDim.x + t; i < total4;
         i += gridDim.x * blockDim.x) {
        float4 v = o4[i];
        int cb = (i & 15) * 4;
        v.x = fmaxf(fmaf(v.x, sc[cb + 0], sh[cb + 0]), 0.0f);
        v.y = fmaxf(fmaf(v.y, sc[cb + 1], sh[cb + 1]), 0.0f);
        v.z = fmaxf(fmaf(v.z, sc[cb + 2], sh[cb + 2]), 0.0f);
        v.w = fmaxf(fmaf(v.w, sc[cb + 3], sh[cb + 3]), 0.0f);
        o4[i] = v;
    }
}

extern "C" void kernel_launch(void* const* d_in, const int* in_sizes, int n_in,
                              void* d_out, int out_size)
{
    const float* features = (const float*)d_in[0];
    const int*   nmap     = (const int*)  d_in[1];
    const float* weight   = (const float*)d_in[2];
    const float* gamma    = (const float*)d_in[3];
    const float* beta     = (const float*)d_in[4];
    float* out = (float*)d_out;

    cudaFuncSetAttribute(conv_mma_kernel,
                         cudaFuncAttributeMaxDynamicSharedMemorySize, SMEM_BYTES);

    prep_w_kernel<<<(KTAPS * C * C + 255) / 256, 256>>>(weight);
    prep_f_kernel<<<N_ROWS * C / 8 / 256, 256>>>((const float4*)features);
    conv_mma_kernel<<<N_ROWS / TILE_M, NTH, SMEM_BYTES>>>(nmap, out);
    norm_relu_kernel<<<1184, 256>>>(out, gamma, beta);
}